// round 3
// baseline (speedup 1.0000x reference)
#include <cuda_runtime.h>
#include <cuda_bf16.h>
#include <math.h>

// Problem constants
#define BB 2
#define TT 2048
#define CC 1024
#define HH 16
#define DD 64
#define RR 512
#define BT (BB*TT)          // 4096
#define KVW (2*HH*DD)       // 2048
#define FFH (4*CC)          // 4096

// ---------------- scratch (device globals; no allocation) ----------------
__device__ float g_h  [BT*CC];     // ln1 out
__device__ float g_lat[BT*RR];     // latent
__device__ float g_kv [BT*KVW];    // kv
__device__ float g_q  [BT*CC];     // q
__device__ float g_y  [BT*CC];     // attention out (B,T,H*D)
__device__ float g_x1 [BT*CC];     // x + y@Wo
__device__ float g_h2 [BT*CC];     // ln2 out
__device__ float g_ff [BT*FFH];    // relu(h2@W1+b1)

// ---------------- LayerNorm ----------------
__inline__ __device__ float warp_sum(float v) {
    #pragma unroll
    for (int o = 16; o > 0; o >>= 1) v += __shfl_xor_sync(0xffffffffu, v, o);
    return v;
}

__global__ void layernorm_k(const float* __restrict__ x,
                            const float* __restrict__ g,
                            const float* __restrict__ b,
                            float* __restrict__ out) {
    int row = blockIdx.x;
    const float* xr = x + (size_t)row * CC;
    float s = 0.f, ss = 0.f;
    for (int i = threadIdx.x; i < CC; i += 256) {
        float v = xr[i];
        s += v; ss += v * v;
    }
    s = warp_sum(s); ss = warp_sum(ss);
    __shared__ float rs[8], rss[8];
    int wid = threadIdx.x >> 5, lane = threadIdx.x & 31;
    if (lane == 0) { rs[wid] = s; rss[wid] = ss; }
    __syncthreads();
    float tot = 0.f, tots = 0.f;
    #pragma unroll
    for (int i = 0; i < 8; i++) { tot += rs[i]; tots += rss[i]; }
    float mean = tot * (1.f / CC);
    float var  = tots * (1.f / CC) - mean * mean;
    float inv  = rsqrtf(var + 1e-5f);
    float* orow = out + (size_t)row * CC;
    for (int i = threadIdx.x; i < CC; i += 256) {
        orow[i] = (xr[i] - mean) * inv * g[i] + b[i];
    }
}

// ---------------- SGEMM 128x128x8, 256 threads, 8x8 microtile ----------------
// C[M,N] = A[M,K] @ B[K,N] (+bias[col]) (+res[row,col]) (relu optional)
template<bool RELU>
__global__ __launch_bounds__(256)
void sgemm_k(int M, int N, int K,
             const float* __restrict__ A,
             const float* __restrict__ B,
             const float* __restrict__ bias,
             const float* __restrict__ res,
             float* __restrict__ C) {
    __shared__ float As[8][128];
    __shared__ float Bs[8][128];

    int tid  = threadIdx.x;
    int brow = blockIdx.y;   // M tile
    int bcol = blockIdx.x;   // N tile
    int tr = tid >> 4;       // 0..15
    int tc = tid & 15;       // 0..15

    const float* Ab = A + (size_t)brow * 128 * K;
    const float* Bb = B + (size_t)bcol * 128;

    float acc[8][8];
    #pragma unroll
    for (int i = 0; i < 8; i++)
        #pragma unroll
        for (int j = 0; j < 8; j++) acc[i][j] = 0.f;

    int aRow = tid >> 1;          // 0..127
    int aCol = (tid & 1) * 4;     // 0/4
    int bRow = tid >> 5;          // 0..7
    int bCol = (tid & 31) * 4;    // 0..124

    for (int k0 = 0; k0 < K; k0 += 8) {
        float4 a4 = *(const float4*)(Ab + (size_t)aRow * K + k0 + aCol);
        As[aCol + 0][aRow] = a4.x;
        As[aCol + 1][aRow] = a4.y;
        As[aCol + 2][aRow] = a4.z;
        As[aCol + 3][aRow] = a4.w;
        float4 b4 = *(const float4*)(Bb + (size_t)(k0 + bRow) * N + bCol);
        *(float4*)&Bs[bRow][bCol] = b4;
        __syncthreads();
        #pragma unroll
        for (int k = 0; k < 8; k++) {
            float ar[8], br[8];
            #pragma unroll
            for (int i = 0; i < 8; i++) ar[i] = As[k][tr * 8 + i];
            #pragma unroll
            for (int j = 0; j < 8; j++) br[j] = Bs[k][tc * 8 + j];
            #pragma unroll
            for (int i = 0; i < 8; i++)
                #pragma unroll
                for (int j = 0; j < 8; j++)
                    acc[i][j] = fmaf(ar[i], br[j], acc[i][j]);
        }
        __syncthreads();
    }

    #pragma unroll
    for (int i = 0; i < 8; i++) {
        int row = brow * 128 + tr * 8 + i;
        #pragma unroll
        for (int j = 0; j < 8; j++) {
            int col = bcol * 128 + tc * 8 + j;
            float v = acc[i][j];
            if (bias) v += bias[col];
            if (res)  v += res[(size_t)row * N + col];
            if (RELU) v = fmaxf(v, 0.f);
            C[(size_t)row * N + col] = v;
        }
    }
}

// ---------------- Flash attention (causal) ----------------
// Br=32 queries per block, Bc=64 keys per tile, D=64.
// 256 threads: tid = r*8 + g ; r=0..31 query row, g=0..7 owns 8 j's / 8 d's.
__global__ __launch_bounds__(256)
void flash_attn_k(const float* __restrict__ Q,   // [BT, H*D]
                  const float* __restrict__ KV,  // [BT, 2*H*D]
                  float* __restrict__ Y) {       // [BT, H*D]
    __shared__ float Qs[32][65];
    __shared__ float Ks[64][65];
    __shared__ float Vs[64][65];

    int qt = blockIdx.x;          // 0..63
    int bh = blockIdx.y;          // 0..31
    int b  = bh >> 4;             // /H
    int h  = bh & 15;             // %H
    int qbase = qt * 32;

    int tid = threadIdx.x;
    int r = tid >> 3;             // 0..31
    int g = tid & 7;              // 0..7
    int lane = tid & 31;
    int laneBase = lane & ~7;

    // load Q tile
    for (int i = 0; i < 8; i++) {
        int e = tid + i * 256;        // 0..2047
        int rr = e >> 6, cc = e & 63;
        Qs[rr][cc] = Q[((size_t)(b * TT + qbase + rr)) * CC + h * DD + cc];
    }

    float m = -1e30f, l = 0.f;
    float o[8];
    #pragma unroll
    for (int i = 0; i < 8; i++) o[i] = 0.f;

    int nkt = (qt >> 1) + 1;      // causal tile bound (Bc = 2*Br)
    for (int kt = 0; kt < nkt; kt++) {
        int kbase = kt * 64;
        // load K and V tiles
        for (int i = 0; i < 16; i++) {
            int e = tid + i * 256;    // 0..4095
            int rr = e >> 6, cc = e & 63;
            size_t base = ((size_t)(b * TT + kbase + rr)) * KVW + h * DD + cc;
            Ks[rr][cc] = KV[base];
            Vs[rr][cc] = KV[base + HH * DD];
        }
        __syncthreads();

        // S = Q K^T / 8 for my 8 columns j = g*8+jj
        float s[8];
        #pragma unroll
        for (int jj = 0; jj < 8; jj++) s[jj] = 0.f;
        #pragma unroll 4
        for (int k = 0; k < 64; k++) {
            float qv = Qs[r][k];
            #pragma unroll
            for (int jj = 0; jj < 8; jj++)
                s[jj] = fmaf(qv, Ks[g * 8 + jj][k], s[jj]);
        }
        int qidx = qbase + r;
        #pragma unroll
        for (int jj = 0; jj < 8; jj++) {
            s[jj] *= 0.125f;   // D^-0.5
            if (kbase + g * 8 + jj > qidx) s[jj] = -1e30f;
        }

        // online softmax
        float mt = s[0];
        #pragma unroll
        for (int jj = 1; jj < 8; jj++) mt = fmaxf(mt, s[jj]);
        #pragma unroll
        for (int off = 1; off < 8; off <<= 1)
            mt = fmaxf(mt, __shfl_xor_sync(0xffffffffu, mt, off));
        float m_new = fmaxf(m, mt);
        float scale = __expf(m - m_new);

        float p[8];
        float lsum = 0.f;
        #pragma unroll
        for (int jj = 0; jj < 8; jj++) {
            p[jj] = __expf(s[jj] - m_new);
            lsum += p[jj];
        }
        #pragma unroll
        for (int off = 1; off < 8; off <<= 1)
            lsum += __shfl_xor_sync(0xffffffffu, lsum, off);
        l = l * scale + lsum;
        #pragma unroll
        for (int dd = 0; dd < 8; dd++) o[dd] *= scale;
        m = m_new;

        // O += P V  (rotate p across the 8-lane row group)
        #pragma unroll
        for (int ph = 0; ph < 8; ph++) {
            int sg = (g + ph) & 7;
            int src = laneBase + sg;
            #pragma unroll
            for (int jj = 0; jj < 8; jj++) {
                float pj = __shfl_sync(0xffffffffu, p[jj], src);
                int j = sg * 8 + jj;
                #pragma unroll
                for (int dd = 0; dd < 8; dd++)
                    o[dd] = fmaf(pj, Vs[j][g * 8 + dd], o[dd]);
            }
        }
        __syncthreads();
    }

    float linv = 1.f / l;
    size_t yb = ((size_t)(b * TT + qbase + r)) * CC + h * DD + g * 8;
    #pragma unroll
    for (int dd = 0; dd < 8; dd++) Y[yb + dd] = o[dd] * linv;
}

// ---------------- launch ----------------
extern "C" void kernel_launch(void* const* d_in, const int* in_sizes, int n_in,
                              void* d_out, int out_size) {
    const float* x       = (const float*)d_in[0];
    const float* ln1_g   = (const float*)d_in[1];
    const float* ln1_b   = (const float*)d_in[2];
    const float* Wkvd    = (const float*)d_in[3];
    const float* Wkvu    = (const float*)d_in[4];
    const float* Wq      = (const float*)d_in[5];
    const float* Wo      = (const float*)d_in[6];
    const float* ln2_g   = (const float*)d_in[7];
    const float* ln2_b   = (const float*)d_in[8];
    const float* Wff1    = (const float*)d_in[9];
    const float* bff1    = (const float*)d_in[10];
    const float* Wff2    = (const float*)d_in[11];
    const float* bff2    = (const float*)d_in[12];
    float* out = (float*)d_out;

    // Resolve scratch addresses once (static: no per-capture API traffic).
    static float* h   = nullptr;
    static float* lat = nullptr;
    static float* kv  = nullptr;
    static float* q   = nullptr;
    static float* y   = nullptr;
    static float* x1  = nullptr;
    static float* h2  = nullptr;
    static float* ff  = nullptr;
    if (!h) {
        void* p;
        cudaGetSymbolAddress(&p, g_h);   h   = (float*)p;
        cudaGetSymbolAddress(&p, g_lat); lat = (float*)p;
        cudaGetSymbolAddress(&p, g_kv);  kv  = (float*)p;
        cudaGetSymbolAddress(&p, g_q);   q   = (float*)p;
        cudaGetSymbolAddress(&p, g_y);   y   = (float*)p;
        cudaGetSymbolAddress(&p, g_x1);  x1  = (float*)p;
        cudaGetSymbolAddress(&p, g_h2);  h2  = (float*)p;
        cudaGetSymbolAddress(&p, g_ff);  ff  = (float*)p;
    }

    // 1) ln1
    layernorm_k<<<BT, 256>>>(x, ln1_g, ln1_b, h);
    // 2) latent = h @ W_kv_down      [4096,512]
    sgemm_k<false><<<dim3(RR/128, BT/128), 256>>>(BT, RR, CC, h, Wkvd, nullptr, nullptr, lat);
    // 3) kv = latent @ W_kv_up       [4096,2048]
    sgemm_k<false><<<dim3(KVW/128, BT/128), 256>>>(BT, KVW, RR, lat, Wkvu, nullptr, nullptr, kv);
    // 4) q = h @ W_q                 [4096,1024]
    sgemm_k<false><<<dim3(CC/128, BT/128), 256>>>(BT, CC, CC, h, Wq, nullptr, nullptr, q);
    // 5) attention -> y
    flash_attn_k<<<dim3(TT/32, BB*HH), 256>>>(q, kv, y);
    // 6) x1 = x + y @ W_o
    sgemm_k<false><<<dim3(CC/128, BT/128), 256>>>(BT, CC, CC, y, Wo, nullptr, x, x1);
    // 7) ln2
    layernorm_k<<<BT, 256>>>(x1, ln2_g, ln2_b, h2);
    // 8) ff = relu(h2 @ W_ff1 + b_ff1)   [4096,4096]
    sgemm_k<true><<<dim3(FFH/128, BT/128), 256>>>(BT, FFH, CC, h2, Wff1, bff1, nullptr, ff);
    // 9) out = ff @ W_ff2 + b_ff2 + x1
    sgemm_k<false><<<dim3(CC/128, BT/128), 256>>>(BT, CC, FFH, ff, Wff2, bff2, x1, out);
}

// round 5
// speedup vs baseline: 1.3700x; 1.3700x over previous
#include <cuda_runtime.h>
#include <cuda_bf16.h>
#include <math.h>
#include <stdint.h>

// Problem constants
#define BB 2
#define TT 2048
#define CC 1024
#define HH 16
#define DD 64
#define RR 512
#define BT (BB*TT)          // 4096
#define KVW (2*HH*DD)       // 2048
#define FFH (4*CC)          // 4096

// ---------------- scratch (device globals; no allocation) ----------------
__device__ float g_h  [BT*CC];     // ln1 out
__device__ float g_lat[BT*RR];     // latent
__device__ float g_kv [BT*KVW];    // kv
__device__ float g_q  [BT*CC];     // q
__device__ float g_y  [BT*CC];     // attention out (B,T,H*D)
__device__ float g_x1 [BT*CC];     // x + y@Wo
__device__ float g_h2 [BT*CC];     // ln2 out
__device__ float g_ff [BT*FFH];    // relu(h2@W1+b1)

// ---------------- LayerNorm ----------------
__inline__ __device__ float warp_sum(float v) {
    #pragma unroll
    for (int o = 16; o > 0; o >>= 1) v += __shfl_xor_sync(0xffffffffu, v, o);
    return v;
}

__global__ void layernorm_k(const float* __restrict__ x,
                            const float* __restrict__ g,
                            const float* __restrict__ b,
                            float* __restrict__ out) {
    int row = blockIdx.x;
    const float* xr = x + (size_t)row * CC;
    float s = 0.f, ss = 0.f;
    for (int i = threadIdx.x; i < CC; i += 256) {
        float v = xr[i];
        s += v; ss += v * v;
    }
    s = warp_sum(s); ss = warp_sum(ss);
    __shared__ float rs[8], rss[8];
    int wid = threadIdx.x >> 5, lane = threadIdx.x & 31;
    if (lane == 0) { rs[wid] = s; rss[wid] = ss; }
    __syncthreads();
    float tot = 0.f, tots = 0.f;
    #pragma unroll
    for (int i = 0; i < 8; i++) { tot += rs[i]; tots += rss[i]; }
    float mean = tot * (1.f / CC);
    float var  = tots * (1.f / CC) - mean * mean;
    float inv  = rsqrtf(var + 1e-5f);
    float* orow = out + (size_t)row * CC;
    for (int i = threadIdx.x; i < CC; i += 256) {
        orow[i] = (xr[i] - mean) * inv * g[i] + b[i];
    }
}

// ---------------- TF32 tensor-core GEMM ----------------
// C[M,N] = A[M,K] @ B[K,N] (+bias[col]) (+res) (relu)
// CTA tile 128x128, K-chunk 32. 8 warps in 4(M) x 2(N); warp tile 32x64.
// mma.sync.m16n8k8.tf32 : per warp 2 m-frags x 8 n-frags.
// Double-buffered dynamic smem, register prefetch of next chunk.

__device__ __forceinline__ uint32_t f2t(float x) {
    uint32_t u;
    asm("cvt.rna.tf32.f32 %0, %1;" : "=r"(u) : "f"(x));
    return u;
}
__device__ __forceinline__ uint4 cvt4(float4 v) {
    return make_uint4(f2t(v.x), f2t(v.y), f2t(v.z), f2t(v.w));
}
__device__ __forceinline__ void mma_tf32(float* d, const uint32_t* a, const uint32_t* b) {
    asm volatile(
        "mma.sync.aligned.m16n8k8.row.col.f32.tf32.tf32.f32 "
        "{%0,%1,%2,%3}, {%4,%5,%6,%7}, {%8,%9}, {%0,%1,%2,%3};"
        : "+f"(d[0]), "+f"(d[1]), "+f"(d[2]), "+f"(d[3])
        : "r"(a[0]), "r"(a[1]), "r"(a[2]), "r"(a[3]),
          "r"(b[0]), "r"(b[1]));
}

#define AP 36               // A smem pitch (words): banks 4m+k -> bijective
#define BP 136              // B smem pitch (words): banks 8k+n -> bijective
#define ASZ (128*AP)        // 4608 words
#define BSZ (32*BP)         // 4352 words
#define GEMM_SMEM_BYTES (2*(ASZ+BSZ)*4)   // 71680

template<bool RELU>
__global__ __launch_bounds__(256)
void gemm_tf32_k(int M, int N, int K,
                 const float* __restrict__ A,
                 const float* __restrict__ B,
                 const float* __restrict__ bias,
                 const float* __restrict__ res,
                 float* __restrict__ C) {
    extern __shared__ uint32_t sm[];
    uint32_t* Asm[2] = { sm,             sm + ASZ + BSZ };
    uint32_t* Bsm[2] = { sm + ASZ,       sm + 2*ASZ + BSZ };

    int tid  = threadIdx.x;
    int wid  = tid >> 5, lane = tid & 31;
    int wm   = wid & 3;          // 0..3  (M)
    int wn   = wid >> 2;         // 0..1  (N)
    int brow = blockIdx.y, bcol = blockIdx.x;

    const float* Ab = A + (size_t)brow * 128 * K;
    const float* Bb = B + (size_t)bcol * 128;

    float acc[2][8][4];
    #pragma unroll
    for (int i = 0; i < 2; i++)
        #pragma unroll
        for (int j = 0; j < 8; j++)
            #pragma unroll
            for (int k = 0; k < 4; k++) acc[i][j][k] = 0.f;

    float4 ra[4], rb[4];

    // ---- load chunk 0 into regs, store to buffer 0 ----
    #pragma unroll
    for (int it = 0; it < 4; it++) {
        int f = tid + it * 256;
        ra[it] = *(const float4*)(Ab + (size_t)(f >> 3) * K + (f & 7) * 4);
        rb[it] = *(const float4*)(Bb + (size_t)(f >> 5) * N + (f & 31) * 4);
    }
    #pragma unroll
    for (int it = 0; it < 4; it++) {
        int f = tid + it * 256;
        *(uint4*)&Asm[0][(f >> 3) * AP + (f & 7) * 4]  = cvt4(ra[it]);
        *(uint4*)&Bsm[0][(f >> 5) * BP + (f & 31) * 4] = cvt4(rb[it]);
    }
    __syncthreads();

    int nc = K >> 5;   // K/32
    for (int c = 0; c < nc; c++) {
        int buf = c & 1;
        if (c + 1 < nc) {
            int k0 = (c + 1) << 5;
            #pragma unroll
            for (int it = 0; it < 4; it++) {
                int f = tid + it * 256;
                ra[it] = *(const float4*)(Ab + (size_t)(f >> 3) * K + k0 + (f & 7) * 4);
                rb[it] = *(const float4*)(Bb + (size_t)(k0 + (f >> 5)) * N + (f & 31) * 4);
            }
        }

        const uint32_t* Ac = Asm[buf];
        const uint32_t* Bc = Bsm[buf];
        int r4 = lane >> 2, c4 = lane & 3;
        #pragma unroll
        for (int ks = 0; ks < 4; ks++) {
            int k8 = ks * 8;
            uint32_t af[2][4];
            #pragma unroll
            for (int mf = 0; mf < 2; mf++) {
                const uint32_t* ap = Ac + (wm * 32 + mf * 16 + r4) * AP + k8 + c4;
                af[mf][0] = ap[0];
                af[mf][1] = ap[8 * AP];
                af[mf][2] = ap[4];
                af[mf][3] = ap[8 * AP + 4];
            }
            uint32_t bf[8][2];
            #pragma unroll
            for (int nf = 0; nf < 8; nf++) {
                const uint32_t* bp = Bc + (k8 + c4) * BP + wn * 64 + nf * 8 + r4;
                bf[nf][0] = bp[0];
                bf[nf][1] = bp[4 * BP];
            }
            #pragma unroll
            for (int mf = 0; mf < 2; mf++)
                #pragma unroll
                for (int nf = 0; nf < 8; nf++)
                    mma_tf32(acc[mf][nf], af[mf], bf[nf]);
        }

        if (c + 1 < nc) {
            #pragma unroll
            for (int it = 0; it < 4; it++) {
                int f = tid + it * 256;
                *(uint4*)&Asm[buf ^ 1][(f >> 3) * AP + (f & 7) * 4]  = cvt4(ra[it]);
                *(uint4*)&Bsm[buf ^ 1][(f >> 5) * BP + (f & 31) * 4] = cvt4(rb[it]);
            }
            __syncthreads();
        }
    }

    // ---- epilogue ----
    int r4 = lane >> 2, c2 = (lane & 3) * 2;
    #pragma unroll
    for (int mf = 0; mf < 2; mf++) {
        #pragma unroll
        for (int nf = 0; nf < 8; nf++) {
            int col = bcol * 128 + wn * 64 + nf * 8 + c2;
            float bz0 = 0.f, bz1 = 0.f;
            if (bias) { bz0 = bias[col]; bz1 = bias[col + 1]; }
            #pragma unroll
            for (int half = 0; half < 2; half++) {
                int row = brow * 128 + wm * 32 + mf * 16 + r4 + half * 8;
                float v0 = acc[mf][nf][half * 2 + 0] + bz0;
                float v1 = acc[mf][nf][half * 2 + 1] + bz1;
                if (res) {
                    const float* rp = res + (size_t)row * N + col;
                    v0 += rp[0]; v1 += rp[1];
                }
                if (RELU) { v0 = fmaxf(v0, 0.f); v1 = fmaxf(v1, 0.f); }
                float2 o = make_float2(v0, v1);
                *(float2*)(C + (size_t)row * N + col) = o;
            }
        }
    }
}

// ---------------- Flash attention (causal) ----------------
// Br=32 queries per block, Bc=64 keys per tile, D=64.
__global__ __launch_bounds__(256)
void flash_attn_k(const float* __restrict__ Q,   // [BT, H*D]
                  const float* __restrict__ KV,  // [BT, 2*H*D]
                  float* __restrict__ Y) {       // [BT, H*D]
    __shared__ float Qs[32][65];
    __shared__ float Ks[64][65];
    __shared__ float Vs[64][65];

    int qt = blockIdx.x;          // 0..63
    int bh = blockIdx.y;          // 0..31
    int b  = bh >> 4;             // /H
    int h  = bh & 15;             // %H
    int qbase = qt * 32;

    int tid = threadIdx.x;
    int r = tid >> 3;             // 0..31
    int g = tid & 7;              // 0..7
    int lane = tid & 31;
    int laneBase = lane & ~7;

    for (int i = 0; i < 8; i++) {
        int e = tid + i * 256;
        int rr = e >> 6, cc = e & 63;
        Qs[rr][cc] = Q[((size_t)(b * TT + qbase + rr)) * CC + h * DD + cc];
    }

    float m = -1e30f, l = 0.f;
    float o[8];
    #pragma unroll
    for (int i = 0; i < 8; i++) o[i] = 0.f;

    int nkt = (qt >> 1) + 1;
    for (int kt = 0; kt < nkt; kt++) {
        int kbase = kt * 64;
        for (int i = 0; i < 16; i++) {
            int e = tid + i * 256;
            int rr = e >> 6, cc = e & 63;
            size_t base = ((size_t)(b * TT + kbase + rr)) * KVW + h * DD + cc;
            Ks[rr][cc] = KV[base];
            Vs[rr][cc] = KV[base + HH * DD];
        }
        __syncthreads();

        float s[8];
        #pragma unroll
        for (int jj = 0; jj < 8; jj++) s[jj] = 0.f;
        #pragma unroll 4
        for (int k = 0; k < 64; k++) {
            float qv = Qs[r][k];
            #pragma unroll
            for (int jj = 0; jj < 8; jj++)
                s[jj] = fmaf(qv, Ks[g * 8 + jj][k], s[jj]);
        }
        int qidx = qbase + r;
        #pragma unroll
        for (int jj = 0; jj < 8; jj++) {
            s[jj] *= 0.125f;
            if (kbase + g * 8 + jj > qidx) s[jj] = -1e30f;
        }

        float mt = s[0];
        #pragma unroll
        for (int jj = 1; jj < 8; jj++) mt = fmaxf(mt, s[jj]);
        #pragma unroll
        for (int off = 1; off < 8; off <<= 1)
            mt = fmaxf(mt, __shfl_xor_sync(0xffffffffu, mt, off));
        float m_new = fmaxf(m, mt);
        float scale = __expf(m - m_new);

        float p[8];
        float lsum = 0.f;
        #pragma unroll
        for (int jj = 0; jj < 8; jj++) {
            p[jj] = __expf(s[jj] - m_new);
            lsum += p[jj];
        }
        #pragma unroll
        for (int off = 1; off < 8; off <<= 1)
            lsum += __shfl_xor_sync(0xffffffffu, lsum, off);
        l = l * scale + lsum;
        #pragma unroll
        for (int dd = 0; dd < 8; dd++) o[dd] *= scale;
        m = m_new;

        #pragma unroll
        for (int ph = 0; ph < 8; ph++) {
            int sg = (g + ph) & 7;
            int src = laneBase + sg;
            #pragma unroll
            for (int jj = 0; jj < 8; jj++) {
                float pj = __shfl_sync(0xffffffffu, p[jj], src);
                int j = sg * 8 + jj;
                #pragma unroll
                for (int dd = 0; dd < 8; dd++)
                    o[dd] = fmaf(pj, Vs[j][g * 8 + dd], o[dd]);
            }
        }
        __syncthreads();
    }

    float linv = 1.f / l;
    size_t yb = ((size_t)(b * TT + qbase + r)) * CC + h * DD + g * 8;
    #pragma unroll
    for (int dd = 0; dd < 8; dd++) Y[yb + dd] = o[dd] * linv;
}

// ---------------- launch ----------------
extern "C" void kernel_launch(void* const* d_in, const int* in_sizes, int n_in,
                              void* d_out, int out_size) {
    const float* x       = (const float*)d_in[0];
    const float* ln1_g   = (const float*)d_in[1];
    const float* ln1_b   = (const float*)d_in[2];
    const float* Wkvd    = (const float*)d_in[3];
    const float* Wkvu    = (const float*)d_in[4];
    const float* Wq      = (const float*)d_in[5];
    const float* Wo      = (const float*)d_in[6];
    const float* ln2_g   = (const float*)d_in[7];
    const float* ln2_b   = (const float*)d_in[8];
    const float* Wff1    = (const float*)d_in[9];
    const float* bff1    = (const float*)d_in[10];
    const float* Wff2    = (const float*)d_in[11];
    const float* bff2    = (const float*)d_in[12];
    float* out = (float*)d_out;

    static float* h   = nullptr;
    static float* lat = nullptr;
    static float* kv  = nullptr;
    static float* q   = nullptr;
    static float* y   = nullptr;
    static float* x1  = nullptr;
    static float* h2  = nullptr;
    static float* ff  = nullptr;
    if (!h) {
        void* p;
        cudaGetSymbolAddress(&p, g_h);   h   = (float*)p;
        cudaGetSymbolAddress(&p, g_lat); lat = (float*)p;
        cudaGetSymbolAddress(&p, g_kv);  kv  = (float*)p;
        cudaGetSymbolAddress(&p, g_q);   q   = (float*)p;
        cudaGetSymbolAddress(&p, g_y);   y   = (float*)p;
        cudaGetSymbolAddress(&p, g_x1);  x1  = (float*)p;
        cudaGetSymbolAddress(&p, g_h2);  h2  = (float*)p;
        cudaGetSymbolAddress(&p, g_ff);  ff  = (float*)p;
        cudaFuncSetAttribute(gemm_tf32_k<false>,
                             cudaFuncAttributeMaxDynamicSharedMemorySize, GEMM_SMEM_BYTES);
        cudaFuncSetAttribute(gemm_tf32_k<true>,
                             cudaFuncAttributeMaxDynamicSharedMemorySize, GEMM_SMEM_BYTES);
    }

    // 1) ln1
    layernorm_k<<<BT, 256>>>(x, ln1_g, ln1_b, h);
    // 2) latent = h @ W_kv_down      [4096,512] K=1024
    gemm_tf32_k<false><<<dim3(RR/128, BT/128), 256, GEMM_SMEM_BYTES>>>(BT, RR, CC, h, Wkvd, nullptr, nullptr, lat);
    // 3) kv = latent @ W_kv_up       [4096,2048] K=512
    gemm_tf32_k<false><<<dim3(KVW/128, BT/128), 256, GEMM_SMEM_BYTES>>>(BT, KVW, RR, lat, Wkvu, nullptr, nullptr, kv);
    // 4) q = h @ W_q                 [4096,1024] K=1024
    gemm_tf32_k<false><<<dim3(CC/128, BT/128), 256, GEMM_SMEM_BYTES>>>(BT, CC, CC, h, Wq, nullptr, nullptr, q);
    // 5) attention -> y
    flash_attn_k<<<dim3(TT/32, BB*HH), 256>>>(q, kv, y);
    // 6) x1 = x + y @ W_o            [4096,1024] K=1024
    gemm_tf32_k<false><<<dim3(CC/128, BT/128), 256, GEMM_SMEM_BYTES>>>(BT, CC, CC, y, Wo, nullptr, x, x1);
    // 7) ln2
    layernorm_k<<<BT, 256>>>(x1, ln2_g, ln2_b, h2);
    // 8) ff = relu(h2 @ W_ff1 + b_ff1)   [4096,4096] K=1024
    gemm_tf32_k<true><<<dim3(FFH/128, BT/128), 256, GEMM_SMEM_BYTES>>>(BT, FFH, CC, h2, Wff1, bff1, nullptr, ff);
    // 9) out = ff @ W_ff2 + b_ff2 + x1   [4096,1024] K=4096
    gemm_tf32_k<false><<<dim3(CC/128, BT/128), 256, GEMM_SMEM_BYTES>>>(BT, CC, FFH, ff, Wff2, bff2, x1, out);
}

// round 8
// speedup vs baseline: 5.6339x; 4.1123x over previous
#include <cuda_runtime.h>
#include <cuda_bf16.h>
#include <math.h>
#include <stdint.h>

// Problem constants
#define BB 2
#define TT 2048
#define CC 1024
#define HH 16
#define DD 64
#define RR 512
#define BT (BB*TT)          // 4096
#define KVW (2*HH*DD)       // 2048
#define FFH (4*CC)          // 4096

// ---------------- scratch (device globals; no allocation) ----------------
__device__ float g_h  [BT*CC];
__device__ float g_lat[BT*RR];
__device__ float g_kv [BT*KVW];
__device__ float g_q  [BT*CC];
__device__ float g_y  [BT*CC];
__device__ float g_x1 [BT*CC];
__device__ float g_h2 [BT*CC];
__device__ float g_ff [BT*FFH];

// ---------------- common helpers ----------------
__device__ __forceinline__ uint32_t f2t(float x) {
    uint32_t u;
    asm("cvt.rna.tf32.f32 %0, %1;" : "=r"(u) : "f"(x));
    return u;
}
__device__ __forceinline__ uint4 cvt4(float4 v) {
    return make_uint4(f2t(v.x), f2t(v.y), f2t(v.z), f2t(v.w));
}
__device__ __forceinline__ void mma_tf32(float* d, const uint32_t* a, const uint32_t* b) {
    asm volatile(
        "mma.sync.aligned.m16n8k8.row.col.f32.tf32.tf32.f32 "
        "{%0,%1,%2,%3}, {%4,%5,%6,%7}, {%8,%9}, {%0,%1,%2,%3};"
        : "+f"(d[0]), "+f"(d[1]), "+f"(d[2]), "+f"(d[3])
        : "r"(a[0]), "r"(a[1]), "r"(a[2]), "r"(a[3]),
          "r"(b[0]), "r"(b[1]));
}

__inline__ __device__ float warp_sum(float v) {
    #pragma unroll
    for (int o = 16; o > 0; o >>= 1) v += __shfl_xor_sync(0xffffffffu, v, o);
    return v;
}

// ---------------- LayerNorm ----------------
__global__ void layernorm_k(const float* __restrict__ x,
                            const float* __restrict__ g,
                            const float* __restrict__ b,
                            float* __restrict__ out) {
    int row = blockIdx.x;
    const float* xr = x + (size_t)row * CC;
    float s = 0.f, ss = 0.f;
    for (int i = threadIdx.x; i < CC; i += 256) {
        float v = xr[i];
        s += v; ss += v * v;
    }
    s = warp_sum(s); ss = warp_sum(ss);
    __shared__ float rs[8], rss[8];
    int wid = threadIdx.x >> 5, lane = threadIdx.x & 31;
    if (lane == 0) { rs[wid] = s; rss[wid] = ss; }
    __syncthreads();
    float tot = 0.f, tots = 0.f;
    #pragma unroll
    for (int i = 0; i < 8; i++) { tot += rs[i]; tots += rss[i]; }
    float mean = tot * (1.f / CC);
    float var  = tots * (1.f / CC) - mean * mean;
    float inv  = rsqrtf(var + 1e-5f);
    float* orow = out + (size_t)row * CC;
    for (int i = threadIdx.x; i < CC; i += 256) {
        orow[i] = (xr[i] - mean) * inv * g[i] + b[i];
    }
}

// ---------------- TF32 tensor-core GEMM (unchanged) ----------------
#define AP 36
#define BP 136
#define ASZ (128*AP)
#define BSZ (32*BP)
#define GEMM_SMEM_BYTES (2*(ASZ+BSZ)*4)   // 71680

template<bool RELU>
__global__ __launch_bounds__(256)
void gemm_tf32_k(int M, int N, int K,
                 const float* __restrict__ A,
                 const float* __restrict__ B,
                 const float* __restrict__ bias,
                 const float* __restrict__ res,
                 float* __restrict__ C) {
    extern __shared__ uint32_t sm[];
    uint32_t* Asm[2] = { sm,             sm + ASZ + BSZ };
    uint32_t* Bsm[2] = { sm + ASZ,       sm + 2*ASZ + BSZ };

    int tid  = threadIdx.x;
    int wid  = tid >> 5, lane = tid & 31;
    int wm   = wid & 3;
    int wn   = wid >> 2;
    int brow = blockIdx.y, bcol = blockIdx.x;

    const float* Ab = A + (size_t)brow * 128 * K;
    const float* Bb = B + (size_t)bcol * 128;

    float acc[2][8][4];
    #pragma unroll
    for (int i = 0; i < 2; i++)
        #pragma unroll
        for (int j = 0; j < 8; j++)
            #pragma unroll
            for (int k = 0; k < 4; k++) acc[i][j][k] = 0.f;

    float4 ra[4], rb[4];

    #pragma unroll
    for (int it = 0; it < 4; it++) {
        int f = tid + it * 256;
        ra[it] = *(const float4*)(Ab + (size_t)(f >> 3) * K + (f & 7) * 4);
        rb[it] = *(const float4*)(Bb + (size_t)(f >> 5) * N + (f & 31) * 4);
    }
    #pragma unroll
    for (int it = 0; it < 4; it++) {
        int f = tid + it * 256;
        *(uint4*)&Asm[0][(f >> 3) * AP + (f & 7) * 4]  = cvt4(ra[it]);
        *(uint4*)&Bsm[0][(f >> 5) * BP + (f & 31) * 4] = cvt4(rb[it]);
    }
    __syncthreads();

    int nc = K >> 5;
    for (int c = 0; c < nc; c++) {
        int buf = c & 1;
        if (c + 1 < nc) {
            int k0 = (c + 1) << 5;
            #pragma unroll
            for (int it = 0; it < 4; it++) {
                int f = tid + it * 256;
                ra[it] = *(const float4*)(Ab + (size_t)(f >> 3) * K + k0 + (f & 7) * 4);
                rb[it] = *(const float4*)(Bb + (size_t)(k0 + (f >> 5)) * N + (f & 31) * 4);
            }
        }

        const uint32_t* Ac = Asm[buf];
        const uint32_t* Bc = Bsm[buf];
        int r4 = lane >> 2, c4 = lane & 3;
        #pragma unroll
        for (int ks = 0; ks < 4; ks++) {
            int k8 = ks * 8;
            uint32_t af[2][4];
            #pragma unroll
            for (int mf = 0; mf < 2; mf++) {
                const uint32_t* ap = Ac + (wm * 32 + mf * 16 + r4) * AP + k8 + c4;
                af[mf][0] = ap[0];
                af[mf][1] = ap[8 * AP];
                af[mf][2] = ap[4];
                af[mf][3] = ap[8 * AP + 4];
            }
            uint32_t bf[8][2];
            #pragma unroll
            for (int nf = 0; nf < 8; nf++) {
                const uint32_t* bp = Bc + (k8 + c4) * BP + wn * 64 + nf * 8 + r4;
                bf[nf][0] = bp[0];
                bf[nf][1] = bp[4 * BP];
            }
            #pragma unroll
            for (int mf = 0; mf < 2; mf++)
                #pragma unroll
                for (int nf = 0; nf < 8; nf++)
                    mma_tf32(acc[mf][nf], af[mf], bf[nf]);
        }

        if (c + 1 < nc) {
            #pragma unroll
            for (int it = 0; it < 4; it++) {
                int f = tid + it * 256;
                *(uint4*)&Asm[buf ^ 1][(f >> 3) * AP + (f & 7) * 4]  = cvt4(ra[it]);
                *(uint4*)&Bsm[buf ^ 1][(f >> 5) * BP + (f & 31) * 4] = cvt4(rb[it]);
            }
            __syncthreads();
        }
    }

    int r4 = lane >> 2, c2 = (lane & 3) * 2;
    #pragma unroll
    for (int mf = 0; mf < 2; mf++) {
        #pragma unroll
        for (int nf = 0; nf < 8; nf++) {
            int col = bcol * 128 + wn * 64 + nf * 8 + c2;
            float bz0 = 0.f, bz1 = 0.f;
            if (bias) { bz0 = bias[col]; bz1 = bias[col + 1]; }
            #pragma unroll
            for (int half = 0; half < 2; half++) {
                int row = brow * 128 + wm * 32 + mf * 16 + r4 + half * 8;
                float v0 = acc[mf][nf][half * 2 + 0] + bz0;
                float v1 = acc[mf][nf][half * 2 + 1] + bz1;
                if (res) {
                    const float* rp = res + (size_t)row * N + col;
                    v0 += rp[0]; v1 += rp[1];
                }
                if (RELU) { v0 = fmaxf(v0, 0.f); v1 = fmaxf(v1, 0.f); }
                float2 o = make_float2(v0, v1);
                *(float2*)(C + (size_t)row * N + col) = o;
            }
        }
    }
}

// ---------------- TF32 tensor-core flash attention (causal) ----------------
// Block: 128 threads (4 warps) x 64 query rows; key tiles of 64.
// S = Q K^T : A = Q (row-major, contraction = dim)
//             B = K read TRANSPOSED (key is the n-axis): Ks[(n_key)*KPK + dim]
// PV        : A = P (contraction = key), B = V key-major (contraction-major)
#define QP  68                         // Qs/Ps pitch (== 4 mod 32)
#define KPK 68                         // Ks pitch: read (nf*8+r4)*KPK + t4 -> banks 4r4+t4
#define KPV 72                         // Vs pitch: read (k8*8+t4)*KPV + r4 -> banks 8t4+r4
#define QS_OFF 0
#define KS_OFF (64*QP)                 // 4352
#define VS_OFF (KS_OFF + 64*KPK)       // 8704
#define PS_OFF (VS_OFF + 64*KPV)       // 13312
#define PS_WARP (16*QP)                // 1088 words per warp
#define FA_SMEM_WORDS (PS_OFF + 4*PS_WARP)   // 17664
#define FA_SMEM_BYTES (FA_SMEM_WORDS*4)      // 70656

__global__ __launch_bounds__(128)
void flash_attn_tc_k(const float* __restrict__ Q,   // [BT, H*D]
                     const float* __restrict__ KV,  // [BT, 2*H*D]
                     float* __restrict__ Y) {       // [BT, H*D]
    extern __shared__ uint32_t sm[];
    uint32_t* Qs = sm + QS_OFF;
    uint32_t* Ks = sm + KS_OFF;
    uint32_t* Vs = sm + VS_OFF;

    int qt = blockIdx.x;              // 0..31 (64-row q tiles)
    int bh = blockIdx.y;              // 0..31
    int b  = bh >> 4;
    int h  = bh & 15;
    int qbase = qt * 64;

    int tid  = threadIdx.x;
    int w    = tid >> 5;
    int lane = tid & 31;
    int r4   = lane >> 2;             // 0..7
    int t4   = lane & 3;              // 0..3
    uint32_t* Ps = sm + PS_OFF + w * PS_WARP;

    // load Q tile (64x64) -> tf32 smem
    #pragma unroll
    for (int i = 0; i < 8; i++) {
        int f = tid + i * 128;            // 0..1023 float4s
        int row = f >> 4, c4 = (f & 15) * 4;
        float4 v = *(const float4*)(Q + ((size_t)(b * TT + qbase + row)) * CC + h * DD + c4);
        *(uint4*)&Qs[row * QP + c4] = cvt4(v);
    }

    float m0 = -1e30f, m1 = -1e30f, l0 = 0.f, l1 = 0.f;
    float acc_o[8][4];
    #pragma unroll
    for (int nf = 0; nf < 8; nf++)
        #pragma unroll
        for (int k = 0; k < 4; k++) acc_o[nf][k] = 0.f;

    int wr = w * 16;
    int nkt = qt + 1;
    for (int kt = 0; kt < nkt; kt++) {
        int kbase = kt * 64;
        // load K and V tiles (64x64 each); rows = keys, cols = dims
        #pragma unroll
        for (int i = 0; i < 8; i++) {
            int f = tid + i * 128;
            int row = f >> 4, c4 = (f & 15) * 4;
            size_t base = ((size_t)(b * TT + kbase + row)) * KVW + h * DD + c4;
            float4 kvv = *(const float4*)(KV + base);
            *(uint4*)&Ks[row * KPK + c4] = cvt4(kvv);
            float4 vvv = *(const float4*)(KV + base + HH * DD);
            *(uint4*)&Vs[row * KPV + c4] = cvt4(vvv);
        }
        __syncthreads();

        // ---- S = Q K^T (warp tile 16x64); contraction over dims ----
        float acc_s[8][4];
        #pragma unroll
        for (int nf = 0; nf < 8; nf++)
            #pragma unroll
            for (int k = 0; k < 4; k++) acc_s[nf][k] = 0.f;

        #pragma unroll
        for (int k8 = 0; k8 < 8; k8++) {
            uint32_t a[4];
            const uint32_t* ap = Qs + (wr + r4) * QP + k8 * 8 + t4;
            a[0] = ap[0];
            a[1] = ap[8 * QP];
            a[2] = ap[4];
            a[3] = ap[8 * QP + 4];
            #pragma unroll
            for (int nf = 0; nf < 8; nf++) {
                // B[k=dim][n=key] = K[key][dim]  (transposed read of key-major Ks)
                uint32_t bfr[2];
                const uint32_t* bp = Ks + (nf * 8 + r4) * KPK + k8 * 8 + t4;
                bfr[0] = bp[0];
                bfr[1] = bp[4];           // dim + 4
                mma_tf32(acc_s[nf], a, bfr);
            }
        }

        // scale + causal mask (diagonal tile only)
        if (kt == qt) {
            int row0 = wr + r4, row1 = row0 + 8;
            #pragma unroll
            for (int nf = 0; nf < 8; nf++) {
                int c0 = nf * 8 + 2 * t4, c1 = c0 + 1;
                acc_s[nf][0] = (c0 > row0) ? -1e30f : acc_s[nf][0] * 0.125f;
                acc_s[nf][1] = (c1 > row0) ? -1e30f : acc_s[nf][1] * 0.125f;
                acc_s[nf][2] = (c0 > row1) ? -1e30f : acc_s[nf][2] * 0.125f;
                acc_s[nf][3] = (c1 > row1) ? -1e30f : acc_s[nf][3] * 0.125f;
            }
        } else {
            #pragma unroll
            for (int nf = 0; nf < 8; nf++)
                #pragma unroll
                for (int k = 0; k < 4; k++) acc_s[nf][k] *= 0.125f;
        }

        // ---- online softmax (two rows per thread) ----
        float mt0 = -1e30f, mt1 = -1e30f;
        #pragma unroll
        for (int nf = 0; nf < 8; nf++) {
            mt0 = fmaxf(mt0, fmaxf(acc_s[nf][0], acc_s[nf][1]));
            mt1 = fmaxf(mt1, fmaxf(acc_s[nf][2], acc_s[nf][3]));
        }
        mt0 = fmaxf(mt0, __shfl_xor_sync(0xffffffffu, mt0, 1));
        mt0 = fmaxf(mt0, __shfl_xor_sync(0xffffffffu, mt0, 2));
        mt1 = fmaxf(mt1, __shfl_xor_sync(0xffffffffu, mt1, 1));
        mt1 = fmaxf(mt1, __shfl_xor_sync(0xffffffffu, mt1, 2));

        float mn0 = fmaxf(m0, mt0), mn1 = fmaxf(m1, mt1);
        float sc0 = __expf(m0 - mn0), sc1 = __expf(m1 - mn1);

        float ls0 = 0.f, ls1 = 0.f;
        #pragma unroll
        for (int nf = 0; nf < 8; nf++) {
            float p0 = __expf(acc_s[nf][0] - mn0);
            float p1 = __expf(acc_s[nf][1] - mn0);
            float p2 = __expf(acc_s[nf][2] - mn1);
            float p3 = __expf(acc_s[nf][3] - mn1);
            ls0 += p0 + p1; ls1 += p2 + p3;
            uint32_t* pp0 = Ps + r4 * QP + nf * 8 + 2 * t4;
            pp0[0]          = f2t(p0);
            pp0[1]          = f2t(p1);
            pp0[8 * QP]     = f2t(p2);
            pp0[8 * QP + 1] = f2t(p3);
        }
        ls0 += __shfl_xor_sync(0xffffffffu, ls0, 1);
        ls0 += __shfl_xor_sync(0xffffffffu, ls0, 2);
        ls1 += __shfl_xor_sync(0xffffffffu, ls1, 1);
        ls1 += __shfl_xor_sync(0xffffffffu, ls1, 2);
        l0 = l0 * sc0 + ls0;
        l1 = l1 * sc1 + ls1;
        m0 = mn0; m1 = mn1;

        #pragma unroll
        for (int nf = 0; nf < 8; nf++) {
            acc_o[nf][0] *= sc0; acc_o[nf][1] *= sc0;
            acc_o[nf][2] *= sc1; acc_o[nf][3] *= sc1;
        }
        __syncwarp();

        // ---- O += P V  (contraction over keys; Vs is key-major) ----
        #pragma unroll
        for (int k8 = 0; k8 < 8; k8++) {
            uint32_t a[4];
            const uint32_t* ap = Ps + r4 * QP + k8 * 8 + t4;
            a[0] = ap[0];
            a[1] = ap[8 * QP];
            a[2] = ap[4];
            a[3] = ap[8 * QP + 4];
            #pragma unroll
            for (int nf = 0; nf < 8; nf++) {
                uint32_t bfr[2];
                const uint32_t* bp = Vs + (k8 * 8 + t4) * KPV + nf * 8 + r4;
                bfr[0] = bp[0];
                bfr[1] = bp[4 * KPV];     // key + 4
                mma_tf32(acc_o[nf], a, bfr);
            }
        }
        __syncthreads();
    }

    // ---- write out ----
    float li0 = 1.f / l0, li1 = 1.f / l1;
    int row0 = qbase + wr + r4;
    #pragma unroll
    for (int nf = 0; nf < 8; nf++) {
        int col = h * DD + nf * 8 + 2 * t4;
        *(float2*)(Y + ((size_t)(b * TT + row0)) * CC + col) =
            make_float2(acc_o[nf][0] * li0, acc_o[nf][1] * li0);
        *(float2*)(Y + ((size_t)(b * TT + row0 + 8)) * CC + col) =
            make_float2(acc_o[nf][2] * li1, acc_o[nf][3] * li1);
    }
}

// ---------------- launch ----------------
extern "C" void kernel_launch(void* const* d_in, const int* in_sizes, int n_in,
                              void* d_out, int out_size) {
    const float* x       = (const float*)d_in[0];
    const float* ln1_g   = (const float*)d_in[1];
    const float* ln1_b   = (const float*)d_in[2];
    const float* Wkvd    = (const float*)d_in[3];
    const float* Wkvu    = (const float*)d_in[4];
    const float* Wq      = (const float*)d_in[5];
    const float* Wo      = (const float*)d_in[6];
    const float* ln2_g   = (const float*)d_in[7];
    const float* ln2_b   = (const float*)d_in[8];
    const float* Wff1    = (const float*)d_in[9];
    const float* bff1    = (const float*)d_in[10];
    const float* Wff2    = (const float*)d_in[11];
    const float* bff2    = (const float*)d_in[12];
    float* out = (float*)d_out;

    static float* h   = nullptr;
    static float* lat = nullptr;
    static float* kv  = nullptr;
    static float* q   = nullptr;
    static float* y   = nullptr;
    static float* x1  = nullptr;
    static float* h2  = nullptr;
    static float* ff  = nullptr;
    if (!h) {
        void* p;
        cudaGetSymbolAddress(&p, g_h);   h   = (float*)p;
        cudaGetSymbolAddress(&p, g_lat); lat = (float*)p;
        cudaGetSymbolAddress(&p, g_kv);  kv  = (float*)p;
        cudaGetSymbolAddress(&p, g_q);   q   = (float*)p;
        cudaGetSymbolAddress(&p, g_y);   y   = (float*)p;
        cudaGetSymbolAddress(&p, g_x1);  x1  = (float*)p;
        cudaGetSymbolAddress(&p, g_h2);  h2  = (float*)p;
        cudaGetSymbolAddress(&p, g_ff);  ff  = (float*)p;
        cudaFuncSetAttribute(gemm_tf32_k<false>,
                             cudaFuncAttributeMaxDynamicSharedMemorySize, GEMM_SMEM_BYTES);
        cudaFuncSetAttribute(gemm_tf32_k<true>,
                             cudaFuncAttributeMaxDynamicSharedMemorySize, GEMM_SMEM_BYTES);
        cudaFuncSetAttribute(flash_attn_tc_k,
                             cudaFuncAttributeMaxDynamicSharedMemorySize, FA_SMEM_BYTES);
    }

    // 1) ln1
    layernorm_k<<<BT, 256>>>(x, ln1_g, ln1_b, h);
    // 2) latent = h @ W_kv_down
    gemm_tf32_k<false><<<dim3(RR/128, BT/128), 256, GEMM_SMEM_BYTES>>>(BT, RR, CC, h, Wkvd, nullptr, nullptr, lat);
    // 3) kv = latent @ W_kv_up
    gemm_tf32_k<false><<<dim3(KVW/128, BT/128), 256, GEMM_SMEM_BYTES>>>(BT, KVW, RR, lat, Wkvu, nullptr, nullptr, kv);
    // 4) q = h @ W_q
    gemm_tf32_k<false><<<dim3(CC/128, BT/128), 256, GEMM_SMEM_BYTES>>>(BT, CC, CC, h, Wq, nullptr, nullptr, q);
    // 5) attention -> y  (tensor-core flash)
    flash_attn_tc_k<<<dim3(TT/64, BB*HH), 128, FA_SMEM_BYTES>>>(q, kv, y);
    // 6) x1 = x + y @ W_o
    gemm_tf32_k<false><<<dim3(CC/128, BT/128), 256, GEMM_SMEM_BYTES>>>(BT, CC, CC, y, Wo, nullptr, x, x1);
    // 7) ln2
    layernorm_k<<<BT, 256>>>(x1, ln2_g, ln2_b, h2);
    // 8) ff = relu(h2 @ W_ff1 + b_ff1)
    gemm_tf32_k<true><<<dim3(FFH/128, BT/128), 256, GEMM_SMEM_BYTES>>>(BT, FFH, CC, h2, Wff1, bff1, nullptr, ff);
    // 9) out = ff @ W_ff2 + b_ff2 + x1
    gemm_tf32_k<false><<<dim3(CC/128, BT/128), 256, GEMM_SMEM_BYTES>>>(BT, CC, FFH, ff, Wff2, bff2, x1, out);
}